// round 7
// baseline (speedup 1.0000x reference)
#include <cuda_runtime.h>

#define T_FRAMES 60
#define HID 32
#define NG 128          // 4*HID gate rows
#define EPSF 1e-5f
#define FULLM 0xffffffffu

// scratch: per-frame input-side gate pre-activations.
// i/f/o rows pre-scaled by 0.5 (sigmoid-via-tanh); g rows unscaled.
__device__ float g_gx[T_FRAMES * NG];
__device__ int   g_done = 0;

__device__ __forceinline__ float tanha(float x) {
    float r; asm("tanh.approx.f32 %0, %1;" : "=f"(r) : "f"(x)); return r;
}

// ---------------------------------------------------------------------------
// Fused kernel: blocks 0..59 = per-frame MLP+LN+W_ih matvec (parallel),
// block 60 = recurrence + output head. One wave (61 blocks < 148 SMs).
// Handoff: frame blocks threadfence + atomicAdd; seq block spins, then reads
// gx from L2 with a 2-step-ahead register prefetch (no smem staging).
// ---------------------------------------------------------------------------
__global__ void __launch_bounds__(128, 1) fused_kernel(
    const float* __restrict__ x,
    const float* __restrict__ w00, const float* __restrict__ b00,
    const float* __restrict__ w01, const float* __restrict__ b01,
    const float* __restrict__ lng, const float* __restrict__ lnb,
    const float* __restrict__ wih, const float* __restrict__ bih,
    const float* __restrict__ bhh,
    const float* __restrict__ whh,
    const float* __restrict__ bng, const float* __restrict__ bnb,
    const float* __restrict__ w10, const float* __restrict__ b10,
    const float* __restrict__ w11, const float* __restrict__ b11,
    const float* __restrict__ w12, const float* __restrict__ b12,
    float* __restrict__ out)
{
    const int tid  = threadIdx.x;
    const int wid  = tid >> 5;
    const int lane = tid & 31;

    if (blockIdx.x < T_FRAMES) {
        // =================== frame path (parallel over t) ===================
        const int t = blockIdx.x;

        __shared__ float sx[63];
        __shared__ float sf1[63];
        __shared__ float sf2[64];
        __shared__ float sfn[64];
        __shared__ float s_mu, s_rstd;

        if (tid < 63) sx[tid] = x[t * 63 + tid];
        __syncthreads();

        if (tid < 63) {
            float acc = b00[tid];
            const float* wr = w00 + tid * 63;
            #pragma unroll
            for (int k = 0; k < 63; k++) acc = fmaf(wr[k], sx[k], acc);
            sf1[tid] = fmaxf(acc, 0.0f);
        }
        __syncthreads();

        if (tid < 64) {
            float acc = b01[tid];
            const float* wr = w01 + tid * 63;
            #pragma unroll
            for (int k = 0; k < 63; k++) acc = fmaf(wr[k], sf1[k], acc);
            sf2[tid] = fmaxf(acc, 0.0f);
        }
        __syncthreads();

        if (tid < 32) {
            float v0 = sf2[tid], v1 = sf2[tid + 32];
            float s = v0 + v1;
            float q = v0 * v0 + v1 * v1;
            #pragma unroll
            for (int o = 16; o > 0; o >>= 1) {
                s += __shfl_xor_sync(FULLM, s, o);
                q += __shfl_xor_sync(FULLM, q, o);
            }
            if (tid == 0) {
                float mu  = s * (1.0f / 64.0f);
                float var = q * (1.0f / 64.0f) - mu * mu;
                s_mu   = mu;
                s_rstd = rsqrtf(var + EPSF);
            }
        }
        __syncthreads();

        if (tid < 64)
            sfn[tid] = (sf2[tid] - s_mu) * s_rstd * lng[tid] + lnb[tid];
        __syncthreads();

        {
            float acc = bih[tid] + bhh[tid];
            const float* wr = wih + tid * 64;
            #pragma unroll
            for (int k = 0; k < 64; k++) acc = fmaf(wr[k], sfn[k], acc);
            // g gate rows (64..95) unscaled; i/f/o rows scaled by 0.5
            float scale = ((tid >> 5) == 2) ? 1.0f : 0.5f;
            g_gx[t * NG + tid] = acc * scale;
        }
        __syncthreads();
        if (tid == 0) {
            __threadfence();
            atomicAdd(&g_done, 1);
        }
        return;
    }

    // ======================= sequential path (block 60) =====================
    // warp w handles gate w (w0=i, w1=f, w2=g, w3=o) for all 32 elements.
    __shared__ __align__(16) float sgate[2][NG];      // [elem*4 + gate]
    __shared__ __align__(16) float shbuf[4][HID];     // per-warp private h copy

    // weights into registers (overlaps with the frame blocks running):
    // lane holds W_hh row (wid*32 + lane); i/f/o warps pre-scaled by 0.5.
    const float wscale = (wid == 2) ? 1.0f : 0.5f;
    float w[HID];
    {
        const float4* wr = reinterpret_cast<const float4*>(whh + (wid * 32 + lane) * HID);
        #pragma unroll
        for (int k4 = 0; k4 < HID / 4; k4++) {
            float4 v = wr[k4];
            w[4 * k4 + 0] = v.x * wscale;
            w[4 * k4 + 1] = v.y * wscale;
            w[4 * k4 + 2] = v.z * wscale;
            w[4 * k4 + 3] = v.w * wscale;
        }
    }

    // wait for all frame blocks
    if (tid == 0) {
        volatile int* p = &g_done;
        while (*p < T_FRAMES) { }
        __threadfence();
    }
    __syncthreads();

    const int gidx = wid * 32 + lane;     // this thread's gx row

    float c, h;

    // ---- t = 0 peeled: h = 0 -> gate is just gx[0] ----
    {
        float g0 = g_gx[gidx];
        float a  = tanha(g0);
        if (wid != 2) a = fmaf(0.5f, a, 0.5f);
        sgate[0][lane * 4 + wid] = a;
        __syncthreads();
        float4 gv = *reinterpret_cast<const float4*>(&sgate[0][lane * 4]); // (i,f,g,o)
        c = gv.x * gv.z;                  // f-gate term vanishes (c0 = 0)
        h = gv.w * tanha(c);
    }

    // 2-step-ahead prefetch of gx from L2
    float p0 = g_gx[1 * NG + gidx];
    float p1 = (T_FRAMES > 2) ? g_gx[2 * NG + gidx] : 0.0f;

    #pragma unroll 1
    for (int t = 1; t < T_FRAMES; t++) {
        // publish h to this warp's private buffer (no cross-warp traffic)
        shbuf[wid][lane] = h;
        float gx0 = p0;
        p0 = p1;
        if (t + 2 < T_FRAMES) p1 = g_gx[(t + 2) * NG + gidx];
        __syncwarp();

        float acc[8];
        acc[0] = gx0;
        #pragma unroll
        for (int i = 1; i < 8; i++) acc[i] = 0.0f;

        #pragma unroll
        for (int k4 = 0; k4 < 8; k4++) {
            float4 hv = *reinterpret_cast<const float4*>(&shbuf[wid][k4 * 4]); // broadcast
            acc[k4] = fmaf(w[4 * k4 + 0], hv.x, acc[k4]);
            acc[k4] = fmaf(w[4 * k4 + 1], hv.y, acc[k4]);
            acc[k4] = fmaf(w[4 * k4 + 2], hv.z, acc[k4]);
            acc[k4] = fmaf(w[4 * k4 + 3], hv.w, acc[k4]);
        }
        float g = ((acc[0] + acc[1]) + (acc[2] + acc[3]))
                + ((acc[4] + acc[5]) + (acc[6] + acc[7]));

        float a = tanha(g);
        if (wid != 2) a = fmaf(0.5f, a, 0.5f);

        float* buf = sgate[t & 1];
        buf[lane * 4 + wid] = a;          // transposed write
        __syncthreads();                  // one barrier per step

        float4 gv = *reinterpret_cast<const float4*>(&buf[lane * 4]); // (i,f,g,o)
        c = fmaf(gv.y, c, gv.x * gv.z);   // every warp keeps its own c
        h = gv.w * tanha(c);              // ... and h (identical across warps)
    }

    // ---- output head ----
    // All warps hold identical h[lane]; two 32x32 layers redundant per warp,
    // final 256-row layer split across warps.
    float hb = (h * rsqrtf(1.0f + EPSF)) * bng[lane] + bnb[lane];

    float o1 = b10[lane];
    #pragma unroll
    for (int k = 0; k < 32; k++)
        o1 = fmaf(w10[lane * 32 + k], __shfl_sync(FULLM, hb, k), o1);
    o1 = fmaxf(o1, 0.0f);

    float o2 = b11[lane];
    #pragma unroll
    for (int k = 0; k < 32; k++)
        o2 = fmaf(w11[lane * 32 + k], __shfl_sync(FULLM, o1, k), o2);
    o2 = fmaxf(o2, 0.0f);

    // warp g -> output rows [64g, 64g+64): 2 rows per lane
    const int r0 = wid * 64 + lane;
    const int r1 = r0 + 32;
    float a0 = b12[r0], a1 = b12[r1];
    #pragma unroll
    for (int k = 0; k < 32; k++) {
        float v = __shfl_sync(FULLM, o2, k);
        a0 = fmaf(w12[r0 * 32 + k], v, a0);
        a1 = fmaf(w12[r1 * 32 + k], v, a1);
    }
    out[r0] = a0;
    out[r1] = a1;

    // reset counter for next replay (all producers already finished; the next
    // launch cannot begin before this kernel completes)
    __syncthreads();
    if (tid == 0) g_done = 0;
}

// ---------------------------------------------------------------------------
// Input order (metadata): x, w00, b00, w01, b01, ln_g, ln_b, w_ih, w_hh,
//                         b_ih, b_hh, bn_g, bn_b, w10, b10, w11, b11, w12, b12
// ---------------------------------------------------------------------------
extern "C" void kernel_launch(void* const* d_in, const int* in_sizes, int n_in,
                              void* d_out, int out_size)
{
    const float* x    = (const float*)d_in[0];
    const float* w00  = (const float*)d_in[1];
    const float* b00  = (const float*)d_in[2];
    const float* w01  = (const float*)d_in[3];
    const float* b01  = (const float*)d_in[4];
    const float* lng  = (const float*)d_in[5];
    const float* lnb  = (const float*)d_in[6];
    const float* wih  = (const float*)d_in[7];
    const float* whh  = (const float*)d_in[8];
    const float* bih  = (const float*)d_in[9];
    const float* bhh  = (const float*)d_in[10];
    const float* bng  = (const float*)d_in[11];
    const float* bnb  = (const float*)d_in[12];
    const float* w10  = (const float*)d_in[13];
    const float* b10  = (const float*)d_in[14];
    const float* w11  = (const float*)d_in[15];
    const float* b11  = (const float*)d_in[16];
    const float* w12  = (const float*)d_in[17];
    const float* b12  = (const float*)d_in[18];
    float* out = (float*)d_out;

    fused_kernel<<<T_FRAMES + 1, 128>>>(
        x, w00, b00, w01, b01, lng, lnb, wih, bih, bhh,
        whh, bng, bnb, w10, b10, w11, b11, w12, b12, out);
}

// round 8
// speedup vs baseline: 1.1207x; 1.1207x over previous
#include <cuda_runtime.h>

#define T_FRAMES 60
#define HID 32
#define NG 128          // 4*HID gate rows
#define EPSF 1e-5f
#define FULLM 0xffffffffu

// scratch: per-frame input-side gate pre-activations.
// i/f/o rows pre-scaled by 0.5 (sigmoid-via-tanh); g rows unscaled.
__device__ float g_gx[T_FRAMES * NG];
__device__ int   g_done = 0;

__device__ __forceinline__ float tanha(float x) {
    float r; asm("tanh.approx.f32 %0, %1;" : "=f"(r) : "f"(x)); return r;
}

// ---------------------------------------------------------------------------
// Fused kernel: blocks 0..59 = per-frame MLP+LN+W_ih matvec (parallel),
// block 60 = recurrence + output head. One wave (61 blocks < 148 SMs).
// Seq block: loads W_hh regs during frame phase, spins on the counter, then
// bulk-stages gx into smem (ldcg) and runs the proven smem-only recurrence.
// ---------------------------------------------------------------------------
__global__ void __launch_bounds__(128, 1) fused_kernel(
    const float* __restrict__ x,
    const float* __restrict__ w00, const float* __restrict__ b00,
    const float* __restrict__ w01, const float* __restrict__ b01,
    const float* __restrict__ lng, const float* __restrict__ lnb,
    const float* __restrict__ wih, const float* __restrict__ bih,
    const float* __restrict__ bhh,
    const float* __restrict__ whh,
    const float* __restrict__ bng, const float* __restrict__ bnb,
    const float* __restrict__ w10, const float* __restrict__ b10,
    const float* __restrict__ w11, const float* __restrict__ b11,
    const float* __restrict__ w12, const float* __restrict__ b12,
    float* __restrict__ out)
{
    const int tid  = threadIdx.x;
    const int wid  = tid >> 5;
    const int lane = tid & 31;

    if (blockIdx.x < T_FRAMES) {
        // =================== frame path (parallel over t) ===================
        const int t = blockIdx.x;

        __shared__ float sx[63];
        __shared__ float sf1[63];
        __shared__ float sf2[64];
        __shared__ float sfn[64];
        __shared__ float s_mu, s_rstd;

        if (tid < 63) sx[tid] = x[t * 63 + tid];
        __syncthreads();

        if (tid < 63) {
            float acc = b00[tid];
            const float* wr = w00 + tid * 63;
            #pragma unroll
            for (int k = 0; k < 63; k++) acc = fmaf(wr[k], sx[k], acc);
            sf1[tid] = fmaxf(acc, 0.0f);
        }
        __syncthreads();

        if (tid < 64) {
            float acc = b01[tid];
            const float* wr = w01 + tid * 63;
            #pragma unroll
            for (int k = 0; k < 63; k++) acc = fmaf(wr[k], sf1[k], acc);
            sf2[tid] = fmaxf(acc, 0.0f);
        }
        __syncthreads();

        if (tid < 32) {
            float v0 = sf2[tid], v1 = sf2[tid + 32];
            float s = v0 + v1;
            float q = v0 * v0 + v1 * v1;
            #pragma unroll
            for (int o = 16; o > 0; o >>= 1) {
                s += __shfl_xor_sync(FULLM, s, o);
                q += __shfl_xor_sync(FULLM, q, o);
            }
            if (tid == 0) {
                float mu  = s * (1.0f / 64.0f);
                float var = q * (1.0f / 64.0f) - mu * mu;
                s_mu   = mu;
                s_rstd = rsqrtf(var + EPSF);
            }
        }
        __syncthreads();

        if (tid < 64)
            sfn[tid] = (sf2[tid] - s_mu) * s_rstd * lng[tid] + lnb[tid];
        __syncthreads();

        {
            float acc = bih[tid] + bhh[tid];
            const float* wr = wih + tid * 64;
            #pragma unroll
            for (int k = 0; k < 64; k++) acc = fmaf(wr[k], sfn[k], acc);
            // g gate rows (64..95) unscaled; i/f/o rows scaled by 0.5
            float scale = ((tid >> 5) == 2) ? 1.0f : 0.5f;
            g_gx[t * NG + tid] = acc * scale;
        }
        __syncthreads();
        if (tid == 0) {
            __threadfence();
            atomicAdd(&g_done, 1);
        }
        return;
    }

    // ======================= sequential path (block 60) =====================
    // warp w handles gate w (w0=i, w1=f, w2=g, w3=o) for all 32 elements.
    __shared__ float sgx[T_FRAMES * NG];              // 30 KB staged gx
    __shared__ __align__(16) float sgate[2][NG];      // [elem*4 + gate]
    __shared__ __align__(16) float shbuf[4][HID];     // per-warp private h copy

    // weights into registers (overlaps with the frame blocks running):
    // lane holds W_hh row (wid*32 + lane); i/f/o warps pre-scaled by 0.5.
    const float wscale = (wid == 2) ? 1.0f : 0.5f;
    float w[HID];
    {
        const float4* wr = reinterpret_cast<const float4*>(whh + (wid * 32 + lane) * HID);
        #pragma unroll
        for (int k4 = 0; k4 < HID / 4; k4++) {
            float4 v = wr[k4];
            w[4 * k4 + 0] = v.x * wscale;
            w[4 * k4 + 1] = v.y * wscale;
            w[4 * k4 + 2] = v.z * wscale;
            w[4 * k4 + 3] = v.w * wscale;
        }
    }

    // wait for all frame blocks
    if (tid == 0) {
        volatile int* p = &g_done;
        while (*p < T_FRAMES) { }
        __threadfence();
    }
    __syncthreads();

    // bulk-stage gx into smem (L2 -> smem, MLP-rich, ~0.7us)
    {
        float4* s4 = reinterpret_cast<float4*>(sgx);
        const float4* g4 = reinterpret_cast<const float4*>(g_gx);
        #pragma unroll
        for (int i = tid; i < (T_FRAMES * NG) / 4; i += 128)
            s4[i] = __ldcg(g4 + i);
    }
    __syncthreads();

    float c, h;

    // ---- t = 0 peeled: h = 0 -> gate is just gx[0] ----
    {
        float g0 = sgx[wid * 32 + lane];
        float a  = tanha(g0);
        if (wid != 2) a = fmaf(0.5f, a, 0.5f);
        sgate[0][lane * 4 + wid] = a;
        __syncthreads();
        float4 gv = *reinterpret_cast<const float4*>(&sgate[0][lane * 4]); // (i,f,g,o)
        c = gv.x * gv.z;                  // f-gate term vanishes (c0 = 0)
        h = gv.w * tanha(c);
    }

    #pragma unroll 1
    for (int t = 1; t < T_FRAMES; t++) {
        // publish h to this warp's private buffer (no cross-warp traffic)
        shbuf[wid][lane] = h;
        float gx0 = sgx[t * NG + wid * 32 + lane];
        __syncwarp();

        float acc[8];
        acc[0] = gx0;
        #pragma unroll
        for (int i = 1; i < 8; i++) acc[i] = 0.0f;

        #pragma unroll
        for (int k4 = 0; k4 < 8; k4++) {
            float4 hv = *reinterpret_cast<const float4*>(&shbuf[wid][k4 * 4]); // broadcast
            acc[k4] = fmaf(w[4 * k4 + 0], hv.x, acc[k4]);
            acc[k4] = fmaf(w[4 * k4 + 1], hv.y, acc[k4]);
            acc[k4] = fmaf(w[4 * k4 + 2], hv.z, acc[k4]);
            acc[k4] = fmaf(w[4 * k4 + 3], hv.w, acc[k4]);
        }
        float g = ((acc[0] + acc[1]) + (acc[2] + acc[3]))
                + ((acc[4] + acc[5]) + (acc[6] + acc[7]));

        float a = tanha(g);
        if (wid != 2) a = fmaf(0.5f, a, 0.5f);

        float* buf = sgate[t & 1];
        buf[lane * 4 + wid] = a;          // transposed write
        __syncthreads();                  // one barrier per step

        float4 gv = *reinterpret_cast<const float4*>(&buf[lane * 4]); // (i,f,g,o)
        c = fmaf(gv.y, c, gv.x * gv.z);   // every warp keeps its own c
        h = gv.w * tanha(c);              // ... and h (identical across warps)
    }

    // ---- output head ----
    // All warps hold identical h[lane]; two 32x32 layers redundant per warp,
    // final 256-row layer split across warps.
    float hb = (h * rsqrtf(1.0f + EPSF)) * bng[lane] + bnb[lane];

    float o1 = b10[lane];
    #pragma unroll
    for (int k = 0; k < 32; k++)
        o1 = fmaf(w10[lane * 32 + k], __shfl_sync(FULLM, hb, k), o1);
    o1 = fmaxf(o1, 0.0f);

    float o2 = b11[lane];
    #pragma unroll
    for (int k = 0; k < 32; k++)
        o2 = fmaf(w11[lane * 32 + k], __shfl_sync(FULLM, o1, k), o2);
    o2 = fmaxf(o2, 0.0f);

    // warp g -> output rows [64g, 64g+64): 2 rows per lane
    const int r0 = wid * 64 + lane;
    const int r1 = r0 + 32;
    float a0 = b12[r0], a1 = b12[r1];
    #pragma unroll
    for (int k = 0; k < 32; k++) {
        float v = __shfl_sync(FULLM, o2, k);
        a0 = fmaf(w12[r0 * 32 + k], v, a0);
        a1 = fmaf(w12[r1 * 32 + k], v, a1);
    }
    out[r0] = a0;
    out[r1] = a1;

    // reset counter for next replay (all producers already finished; the next
    // launch cannot begin before this kernel completes)
    __syncthreads();
    if (tid == 0) g_done = 0;
}

// ---------------------------------------------------------------------------
// Input order (metadata): x, w00, b00, w01, b01, ln_g, ln_b, w_ih, w_hh,
//                         b_ih, b_hh, bn_g, bn_b, w10, b10, w11, b11, w12, b12
// ---------------------------------------------------------------------------
extern "C" void kernel_launch(void* const* d_in, const int* in_sizes, int n_in,
                              void* d_out, int out_size)
{
    const float* x    = (const float*)d_in[0];
    const float* w00  = (const float*)d_in[1];
    const float* b00  = (const float*)d_in[2];
    const float* w01  = (const float*)d_in[3];
    const float* b01  = (const float*)d_in[4];
    const float* lng  = (const float*)d_in[5];
    const float* lnb  = (const float*)d_in[6];
    const float* wih  = (const float*)d_in[7];
    const float* whh  = (const float*)d_in[8];
    const float* bih  = (const float*)d_in[9];
    const float* bhh  = (const float*)d_in[10];
    const float* bng  = (const float*)d_in[11];
    const float* bnb  = (const float*)d_in[12];
    const float* w10  = (const float*)d_in[13];
    const float* b10  = (const float*)d_in[14];
    const float* w11  = (const float*)d_in[15];
    const float* b11  = (const float*)d_in[16];
    const float* w12  = (const float*)d_in[17];
    const float* b12  = (const float*)d_in[18];
    float* out = (float*)d_out;

    fused_kernel<<<T_FRAMES + 1, 128>>>(
        x, w00, b00, w01, b01, lng, lnb, wih, bih, bhh,
        whh, bng, bnb, w10, b10, w11, b11, w12, b12, out);
}